// round 13
// baseline (speedup 1.0000x reference)
#include <cuda_runtime.h>
#include <math.h>

#define N_NODES 20000
#define N_EDGES 640000
#define HID     256
#define IN_FLAT 36
#define EDGE_DIM 8
#define T_DIM   4
#define S_DIM   6
#define N_LAYERS 5
#define OUT_DIM 18

// ---------------- scratch (device globals; no allocation allowed) ----------
__device__ float g_h[N_NODES * HID];
__device__ float g_u[N_NODES * (3 * HID)];
__device__ float g_q[N_NODES * HID];
__device__ float g_k[N_NODES * HID];
__device__ float g_v[N_NODES * HID];
__device__ float g_skip[N_NODES * HID];
__device__ int   g_cnt[N_NODES];
__device__ int   g_rowptr[N_NODES + 1];
__device__ int   g_cursor[N_NODES];
__device__ int   g_perm[N_EDGES];

// ---------------- CSR build -------------------------------------------------
__global__ void zero_cnt_kernel() {
    for (int i = blockIdx.x * blockDim.x + threadIdx.x; i < N_NODES;
         i += gridDim.x * blockDim.x)
        g_cnt[i] = 0;
}

__global__ void count_kernel(const int* __restrict__ dst) {
    int e = blockIdx.x * blockDim.x + threadIdx.x;
    if (e < N_EDGES) atomicAdd(&g_cnt[dst[e]], 1);
}

// scan also initializes g_cursor (exclusive prefix) — cursor_init folded in
__global__ void scan_kernel() {
    __shared__ int sh[1024];
    __shared__ int carry;
    int tid = threadIdx.x;
    if (tid == 0) { carry = 0; g_rowptr[0] = 0; }
    __syncthreads();
    for (int base = 0; base < N_NODES; base += 1024) {
        int i = base + tid;
        int vv = (i < N_NODES) ? g_cnt[i] : 0;
        sh[tid] = vv;
        __syncthreads();
        #pragma unroll
        for (int off = 1; off < 1024; off <<= 1) {
            int t = (tid >= off) ? sh[tid - off] : 0;
            __syncthreads();
            sh[tid] += t;
            __syncthreads();
        }
        if (i < N_NODES) {
            int inc = carry + sh[tid];
            g_rowptr[i + 1] = inc;
            g_cursor[i] = inc - vv;
        }
        __syncthreads();
        if (tid == 0) carry += sh[1023];
        __syncthreads();
    }
}

__global__ void fill_kernel(const int* __restrict__ dst) {
    int e = blockIdx.x * blockDim.x + threadIdx.x;
    if (e < N_EDGES) {
        int pos = atomicAdd(&g_cursor[dst[e]], 1);
        g_perm[pos] = e;
    }
}

// ---------------- embedding: u = [x@W_emb+b | t@W_t+b | s@W_s+b] ------------
__global__ __launch_bounds__(256) void embed_kernel(
    const float* __restrict__ x, const float* __restrict__ t,
    const float* __restrict__ s,
    const float* __restrict__ W_emb, const float* __restrict__ b_emb,
    const float* __restrict__ W_t, const float* __restrict__ b_t,
    const float* __restrict__ W_s, const float* __restrict__ b_s)
{
    __shared__ float xs[IN_FLAT + T_DIM + S_DIM];
    int node = blockIdx.x;
    int tid  = threadIdx.x;
    if (tid < IN_FLAT) xs[tid] = x[node * IN_FLAT + tid];
    else if (tid < IN_FLAT + T_DIM) xs[tid] = t[node * T_DIM + (tid - IN_FLAT)];
    else if (tid < IN_FLAT + T_DIM + S_DIM)
        xs[tid] = s[node * S_DIM + (tid - IN_FLAT - T_DIM)];
    __syncthreads();

    float a = b_emb[tid];
    #pragma unroll
    for (int k = 0; k < IN_FLAT; k++) a = fmaf(xs[k], W_emb[k * HID + tid], a);
    float tt = b_t[tid];
    #pragma unroll
    for (int k = 0; k < T_DIM; k++) tt = fmaf(xs[IN_FLAT + k], W_t[k * HID + tid], tt);
    float ss = b_s[tid];
    #pragma unroll
    for (int k = 0; k < S_DIM; k++)
        ss = fmaf(xs[IN_FLAT + T_DIM + k], W_s[k * HID + tid], ss);

    g_u[node * 768 + tid]       = a;
    g_u[node * 768 + 256 + tid] = tt;
    g_u[node * 768 + 512 + tid] = ss;
}

// ---------------- tf32 tensor-core GEMM ------------------------------------
__device__ __forceinline__ unsigned f2tf32(float x) {
    unsigned r;
    asm("cvt.rna.tf32.f32 %0, %1;" : "=r"(r) : "f"(x));
    return r;
}

__global__ __launch_bounds__(256) void gemm_tf32_kernel(
    const float* __restrict__ A, int M, int K,
    const float* __restrict__ W0, const float* __restrict__ W1,
    const float* __restrict__ W2, const float* __restrict__ W3,
    const float* __restrict__ b0, const float* __restrict__ b1,
    const float* __restrict__ b2, const float* __restrict__ b3,
    float* __restrict__ C0, float* __restrict__ C1,
    float* __restrict__ C2, float* __restrict__ C3)
{
    const float* W; const float* bias; float* C;
    switch (blockIdx.z) {
        case 0: W = W0; bias = b0; C = C0; break;
        case 1: W = W1; bias = b1; C = C1; break;
        case 2: W = W2; bias = b2; C = C2; break;
        default: W = W3; bias = b3; C = C3; break;
    }

    __shared__ unsigned As[4096];
    __shared__ unsigned Bs[4096];

    int tid = threadIdx.x;
    int lane = tid & 31, warp = tid >> 5;
    int wm = warp >> 1, wn = warp & 1;
    int m0 = blockIdx.y * 128;
    int n0 = blockIdx.x * 128;

    float acc[2][8][4];
    #pragma unroll
    for (int mt = 0; mt < 2; mt++)
        #pragma unroll
        for (int j = 0; j < 8; j++)
            #pragma unroll
            for (int r = 0; r < 4; r++) acc[mt][j][r] = 0.f;

    for (int k0 = 0; k0 < K; k0 += 32) {
        #pragma unroll
        for (int i = 0; i < 4; i++) {
            int idx = tid + 256 * i;
            int row = idx >> 3;
            int c4  = idx & 7;
            int gr = m0 + row;
            float4 av = make_float4(0.f, 0.f, 0.f, 0.f);
            if (gr < M)
                av = *reinterpret_cast<const float4*>(A + (size_t)gr * K + k0 + c4 * 4);
            float vv[4] = {av.x, av.y, av.z, av.w};
            int tm = row >> 4, mr = row & 15;
            #pragma unroll
            for (int j = 0; j < 4; j++) {
                int kl = c4 * 4 + j;
                int tk = kl >> 3, kr = kl & 7;
                int ln = ((mr & 7) << 2) | (kr & 3);
                int rg = (mr >> 3) | ((kr >> 2) << 1);
                As[(((tm * 4 + tk) * 32 + ln) << 2) + rg] = f2tf32(vv[j]);
            }
        }
        #pragma unroll
        for (int i = 0; i < 4; i++) {
            int idx = tid + 256 * i;
            int kl = idx >> 5;
            int c4 = idx & 31;
            float4 bv = *reinterpret_cast<const float4*>(
                W + (size_t)(k0 + kl) * HID + n0 + c4 * 4);
            float vv[4] = {bv.x, bv.y, bv.z, bv.w};
            int tk = kl >> 3, kr = kl & 7;
            #pragma unroll
            for (int j = 0; j < 4; j++) {
                int nl = c4 * 4 + j;
                int tn = nl >> 3, nr = nl & 7;
                int ln = (nr << 2) | (kr & 3);
                int rg = kr >> 2;
                Bs[(((tn * 4 + tk) * 32 + ln) << 1) + rg] = f2tf32(vv[j]);
            }
        }
        __syncthreads();

        #pragma unroll
        for (int tk = 0; tk < 4; tk++) {
            uint4 af[2];
            #pragma unroll
            for (int mt = 0; mt < 2; mt++)
                af[mt] = *reinterpret_cast<const uint4*>(
                    &As[(((wm * 2 + mt) * 4 + tk) * 32 + lane) << 2]);
            uint2 bf[8];
            #pragma unroll
            for (int j = 0; j < 8; j++)
                bf[j] = *reinterpret_cast<const uint2*>(
                    &Bs[(((wn * 8 + j) * 4 + tk) * 32 + lane) << 1]);
            #pragma unroll
            for (int mt = 0; mt < 2; mt++)
                #pragma unroll
                for (int j = 0; j < 8; j++) {
                    asm volatile(
                        "mma.sync.aligned.m16n8k8.row.col.f32.tf32.tf32.f32 "
                        "{%0,%1,%2,%3},{%4,%5,%6,%7},{%8,%9},{%0,%1,%2,%3};\n"
                        : "+f"(acc[mt][j][0]), "+f"(acc[mt][j][1]),
                          "+f"(acc[mt][j][2]), "+f"(acc[mt][j][3])
                        : "r"(af[mt].x), "r"(af[mt].y), "r"(af[mt].z), "r"(af[mt].w),
                          "r"(bf[j].x), "r"(bf[j].y));
                }
        }
        __syncthreads();
    }

    #pragma unroll
    for (int j = 0; j < 8; j++) {
        int col = n0 + (wn * 8 + j) * 8 + 2 * (lane & 3);
        float bx = bias[col], by = bias[col + 1];
        #pragma unroll
        for (int mt = 0; mt < 2; mt++) {
            int r0 = m0 + (wm * 2 + mt) * 16 + (lane >> 2);
            if (r0 < M) {
                float2 o = make_float2(acc[mt][j][0] + bx, acc[mt][j][1] + by);
                *reinterpret_cast<float2*>(C + (size_t)r0 * HID + col) = o;
            }
            int r1 = r0 + 8;
            if (r1 < M) {
                float2 o = make_float2(acc[mt][j][2] + bx, acc[mt][j][3] + by);
                *reinterpret_cast<float2*>(C + (size_t)r1 * HID + col) = o;
            }
        }
    }
}

// ---------------- layernorm + relu (in place on g_h) ------------------------
__global__ __launch_bounds__(256) void ln_relu_kernel(
    const float* __restrict__ gam, const float* __restrict__ bet,
    float* __restrict__ h)
{
    int node = blockIdx.x, tid = threadIdx.x;
    float v = h[node * HID + tid];
    __shared__ float red[8];

    float s1 = v;
    #pragma unroll
    for (int o = 16; o; o >>= 1) s1 += __shfl_xor_sync(0xffffffffu, s1, o);
    if ((tid & 31) == 0) red[tid >> 5] = s1;
    __syncthreads();
    float tot = 0.f;
    #pragma unroll
    for (int i = 0; i < 8; i++) tot += red[i];
    float mu = tot * (1.0f / HID);
    float d = v - mu;

    float s2 = d * d;
    #pragma unroll
    for (int o = 16; o; o >>= 1) s2 += __shfl_xor_sync(0xffffffffu, s2, o);
    __syncthreads();
    if ((tid & 31) == 0) red[tid >> 5] = s2;
    __syncthreads();
    float tot2 = 0.f;
    #pragma unroll
    for (int i = 0; i < 8; i++) tot2 += red[i];
    float var = tot2 * (1.0f / HID);

    float y = d * rsqrtf(var + 1e-5f) * gam[tid] + bet[tid];
    h[node * HID + tid] = fmaxf(y, 0.f);
}

// ---------------- edge attention: warp per destination node -----------------
// R5 edge body (strided lane mapping, 4-edge unroll, no-max softmax) with
// qprep (qe8 = We@q, qbe = be.q) inlined at warp start.
__global__ __launch_bounds__(256, 2) void edge_attn_kernel(
    const int* __restrict__ src, const float* __restrict__ edge_attr,
    const float* __restrict__ We, const float* __restrict__ be,
    const float* __restrict__ q, const float* __restrict__ k,
    const float* __restrict__ v, const float* __restrict__ skp,
    float* __restrict__ h_out)
{
    int node = (blockIdx.x * blockDim.x + threadIdx.x) >> 5;
    int lane = threadIdx.x & 31;
    if (node >= N_NODES) return;

    float qr[8];
    #pragma unroll
    for (int i = 0; i < 8; i++) qr[i] = q[(size_t)node * HID + lane + 32 * i];

    // inline qprep: qe8[j] = (We @ q)[j], qbe = be . q
    float part[9];
    #pragma unroll
    for (int j = 0; j < 8; j++) {
        float pq = 0.f;
        #pragma unroll
        for (int i = 0; i < 8; i++)
            pq = fmaf(qr[i], We[j * HID + lane + 32 * i], pq);
        part[j] = pq;
    }
    {
        float pq = 0.f;
        #pragma unroll
        for (int i = 0; i < 8; i++) pq = fmaf(qr[i], be[lane + 32 * i], pq);
        part[8] = pq;
    }
    #pragma unroll
    for (int o = 16; o; o >>= 1)
        #pragma unroll
        for (int j = 0; j < 9; j++)
            part[j] += __shfl_xor_sync(0xffffffffu, part[j], o);
    float qe8v = (lane < 8) ? part[lane] : 0.f;
    float qbev = part[8];

    float acc[8];
    #pragma unroll
    for (int i = 0; i < 8; i++) acc[i] = 0.f;
    float accE = 0.f;
    float l = 0.f;

    int beg = g_rowptr[node], end = g_rowptr[node + 1];
    int p = beg;

    for (; p + 4 <= end; p += 4) {
        int e0 = g_perm[p],     e1 = g_perm[p + 1];
        int e2 = g_perm[p + 2], e3 = g_perm[p + 3];
        int s0 = src[e0], s1 = src[e1], s2 = src[e2], s3 = src[e3];
        float ea0 = (lane < 8) ? edge_attr[(size_t)e0 * EDGE_DIM + lane] : 0.f;
        float ea1 = (lane < 8) ? edge_attr[(size_t)e1 * EDGE_DIM + lane] : 0.f;
        float ea2 = (lane < 8) ? edge_attr[(size_t)e2 * EDGE_DIM + lane] : 0.f;
        float ea3 = (lane < 8) ? edge_attr[(size_t)e3 * EDGE_DIM + lane] : 0.f;
        const float* k0 = k + (size_t)s0 * HID + lane;
        const float* k1 = k + (size_t)s1 * HID + lane;
        const float* k2 = k + (size_t)s2 * HID + lane;
        const float* k3 = k + (size_t)s3 * HID + lane;

        float d0 = ea0 * qe8v, d1 = ea1 * qe8v;
        float d2 = ea2 * qe8v, d3 = ea3 * qe8v;
        #pragma unroll
        for (int i = 0; i < 8; i++) {
            d0 = fmaf(qr[i], k0[32 * i], d0);
            d1 = fmaf(qr[i], k1[32 * i], d1);
            d2 = fmaf(qr[i], k2[32 * i], d2);
            d3 = fmaf(qr[i], k3[32 * i], d3);
        }
        #pragma unroll
        for (int o = 16; o; o >>= 1) {
            d0 += __shfl_xor_sync(0xffffffffu, d0, o);
            d1 += __shfl_xor_sync(0xffffffffu, d1, o);
            d2 += __shfl_xor_sync(0xffffffffu, d2, o);
            d3 += __shfl_xor_sync(0xffffffffu, d3, o);
        }
        float pw0 = __expf((d0 + qbev) * 0.0625f);
        float pw1 = __expf((d1 + qbev) * 0.0625f);
        float pw2 = __expf((d2 + qbev) * 0.0625f);
        float pw3 = __expf((d3 + qbev) * 0.0625f);
        l += (pw0 + pw1) + (pw2 + pw3);
        accE = fmaf(pw0, ea0, accE);
        accE = fmaf(pw1, ea1, accE);
        accE = fmaf(pw2, ea2, accE);
        accE = fmaf(pw3, ea3, accE);
        const float* v0 = v + (size_t)s0 * HID + lane;
        const float* v1 = v + (size_t)s1 * HID + lane;
        const float* v2 = v + (size_t)s2 * HID + lane;
        const float* v3 = v + (size_t)s3 * HID + lane;
        #pragma unroll
        for (int i = 0; i < 8; i++) {
            float t0 = fmaf(pw0, v0[32 * i], pw1 * v1[32 * i]);
            float t1 = fmaf(pw2, v2[32 * i], pw3 * v3[32 * i]);
            acc[i] += t0 + t1;
        }
    }
    for (; p < end; p++) {
        int e0 = g_perm[p];
        int s0 = src[e0];
        float ea0 = (lane < 8) ? edge_attr[(size_t)e0 * EDGE_DIM + lane] : 0.f;
        const float* k0 = k + (size_t)s0 * HID + lane;
        float d0 = ea0 * qe8v;
        #pragma unroll
        for (int i = 0; i < 8; i++) d0 = fmaf(qr[i], k0[32 * i], d0);
        #pragma unroll
        for (int o = 16; o; o >>= 1) d0 += __shfl_xor_sync(0xffffffffu, d0, o);
        float pw0 = __expf((d0 + qbev) * 0.0625f);
        l += pw0;
        accE = fmaf(pw0, ea0, accE);
        const float* v0 = v + (size_t)s0 * HID + lane;
        #pragma unroll
        for (int i = 0; i < 8; i++) acc[i] = fmaf(pw0, v0[32 * i], acc[i]);
    }

    // epilogue: out = (acc + accE@We + l*be)/l + skip, relu
    float accEj[8];
    #pragma unroll
    for (int j = 0; j < 8; j++)
        accEj[j] = __shfl_sync(0xffffffffu, accE, j);
    float inv = 1.0f / (l + 1e-16f);
    #pragma unroll
    for (int i = 0; i < 8; i++) {
        int c = lane + 32 * i;
        float corr = l * be[c];
        #pragma unroll
        for (int j = 0; j < 8; j++)
            corr = fmaf(accEj[j], We[j * HID + c], corr);
        float o = (acc[i] + corr) * inv + skp[(size_t)node * HID + c];
        h_out[(size_t)node * HID + c] = fmaxf(o, 0.f);
    }
}

// ---------------- decoder: out = h @ W_dec + b_dec --------------------------
__global__ __launch_bounds__(256) void decoder_kernel(
    const float* __restrict__ h, const float* __restrict__ Wd,
    const float* __restrict__ bd, float* __restrict__ out)
{
    __shared__ float Ws[HID * OUT_DIM];
    for (int i = threadIdx.x; i < HID * OUT_DIM; i += blockDim.x) Ws[i] = Wd[i];
    __syncthreads();
    for (int idx = blockIdx.x * blockDim.x + threadIdx.x; idx < N_NODES * OUT_DIM;
         idx += gridDim.x * blockDim.x) {
        int node = idx / OUT_DIM;
        int c = idx - node * OUT_DIM;
        float sum = bd[c];
        const float* hr = h + (size_t)node * HID;
        #pragma unroll 8
        for (int k2 = 0; k2 < HID; k2++)
            sum = fmaf(hr[k2], Ws[k2 * OUT_DIM + c], sum);
        out[idx] = sum;
    }
}

// ---------------- launch ----------------------------------------------------
extern "C" void kernel_launch(void* const* d_in, const int* in_sizes, int n_in,
                              void* d_out, int out_size)
{
    const float* x        = (const float*)d_in[0];
    const int*   edge_idx = (const int*)  d_in[1];
    const float* edge_attr= (const float*)d_in[2];
    const float* t        = (const float*)d_in[3];
    const float* s        = (const float*)d_in[4];
    const float* W_emb    = (const float*)d_in[5];
    const float* b_emb    = (const float*)d_in[6];
    const float* W_t      = (const float*)d_in[7];
    const float* b_t      = (const float*)d_in[8];
    const float* W_s      = (const float*)d_in[9];
    const float* b_s      = (const float*)d_in[10];
    const float* W_f      = (const float*)d_in[11];
    const float* b_f      = (const float*)d_in[12];
    const float* ln_g     = (const float*)d_in[13];
    const float* ln_b     = (const float*)d_in[14];
    const float* Wq       = (const float*)d_in[15];
    const float* bq       = (const float*)d_in[16];
    const float* Wk       = (const float*)d_in[17];
    const float* bk       = (const float*)d_in[18];
    const float* Wv       = (const float*)d_in[19];
    const float* bv       = (const float*)d_in[20];
    const float* We       = (const float*)d_in[21];
    const float* be       = (const float*)d_in[22];
    const float* Wskip    = (const float*)d_in[23];
    const float* bskip    = (const float*)d_in[24];
    const float* W_dec    = (const float*)d_in[25];
    const float* b_dec    = (const float*)d_in[26];
    float* out = (float*)d_out;

    const int* src = edge_idx;
    const int* dst = edge_idx + N_EDGES;

    float *p_h, *p_u, *p_q, *p_k, *p_v, *p_skip;
    cudaGetSymbolAddress((void**)&p_h, g_h);
    cudaGetSymbolAddress((void**)&p_u, g_u);
    cudaGetSymbolAddress((void**)&p_q, g_q);
    cudaGetSymbolAddress((void**)&p_k, g_k);
    cudaGetSymbolAddress((void**)&p_v, g_v);
    cudaGetSymbolAddress((void**)&p_skip, g_skip);

    // CSR by destination
    zero_cnt_kernel<<<80, 256>>>();
    count_kernel<<<(N_EDGES + 255) / 256, 256>>>(dst);
    scan_kernel<<<1, 1024>>>();
    fill_kernel<<<(N_EDGES + 255) / 256, 256>>>(dst);

    // spatio-temporal embedding + fusion GEMM + LN + relu
    embed_kernel<<<N_NODES, 256>>>(x, t, s, W_emb, b_emb, W_t, b_t, W_s, b_s);
    dim3 fgrid(2, (N_NODES + 127) / 128, 1);
    gemm_tf32_kernel<<<fgrid, 256>>>(p_u, N_NODES, 3 * HID,
        W_f, W_f, W_f, W_f, b_f, b_f, b_f, b_f, p_h, p_h, p_h, p_h);
    ln_relu_kernel<<<N_NODES, 256>>>(ln_g, ln_b, p_h);

    // 5 TransformerConv layers
    dim3 qgrid(2, (N_NODES + 127) / 128, 4);
    int warps_grid = (N_NODES * 32 + 255) / 256;
    for (int l = 0; l < N_LAYERS; l++) {
        const float* We_l = We + (size_t)l * EDGE_DIM * HID;
        const float* be_l = be + l * HID;
        gemm_tf32_kernel<<<qgrid, 256>>>(p_h, N_NODES, HID,
            Wq + (size_t)l * HID * HID, Wk + (size_t)l * HID * HID,
            Wv + (size_t)l * HID * HID, Wskip + (size_t)l * HID * HID,
            bq + l * HID, bk + l * HID, bv + l * HID, bskip + l * HID,
            p_q, p_k, p_v, p_skip);
        edge_attn_kernel<<<warps_grid, 256>>>(
            src, edge_attr, We_l, be_l, p_q, p_k, p_v, p_skip, p_h);
    }

    // decoder
    decoder_kernel<<<592, 256>>>(p_h, W_dec, b_dec, out);
}

// round 17
// speedup vs baseline: 1.2578x; 1.2578x over previous
#include <cuda_runtime.h>
#include <math.h>

#define N_NODES 20000
#define N_EDGES 640000
#define HID     256
#define IN_FLAT 36
#define EDGE_DIM 8
#define T_DIM   4
#define S_DIM   6
#define N_LAYERS 5
#define OUT_DIM 18
#define DBINS   512

// ---------------- scratch (device globals; no allocation allowed) ----------
__device__ float g_h[N_NODES * HID];
__device__ float g_u[N_NODES * (3 * HID)];
__device__ float g_q[N_NODES * HID];
__device__ float g_k[N_NODES * HID];
__device__ float g_v[N_NODES * HID];
__device__ float g_skip[N_NODES * HID];
__device__ float g_qe8[N_NODES * EDGE_DIM];
__device__ float g_qbe[N_NODES];
__device__ int   g_cnt[N_NODES];
__device__ int   g_rowptr[N_NODES + 1];
__device__ int   g_cursor[N_NODES];
__device__ int   g_perm[N_EDGES];
__device__ int   g_hcnt[DBINS];
__device__ int   g_order[N_NODES];

// ---------------- CSR build -------------------------------------------------
__global__ void zero_cnt_kernel() {
    for (int i = blockIdx.x * blockDim.x + threadIdx.x; i < N_NODES;
         i += gridDim.x * blockDim.x) {
        g_cnt[i] = 0;
        if (i < DBINS) g_hcnt[i] = 0;
    }
}

__global__ void count_kernel(const int* __restrict__ dst) {
    int e = blockIdx.x * blockDim.x + threadIdx.x;
    if (e < N_EDGES) atomicAdd(&g_cnt[dst[e]], 1);
}

// scan also initializes g_cursor (exclusive prefix) — cursor_init folded in
__global__ void scan_kernel() {
    __shared__ int sh[1024];
    __shared__ int carry;
    int tid = threadIdx.x;
    if (tid == 0) { carry = 0; g_rowptr[0] = 0; }
    __syncthreads();
    for (int base = 0; base < N_NODES; base += 1024) {
        int i = base + tid;
        int vv = (i < N_NODES) ? g_cnt[i] : 0;
        sh[tid] = vv;
        __syncthreads();
        #pragma unroll
        for (int off = 1; off < 1024; off <<= 1) {
            int t = (tid >= off) ? sh[tid - off] : 0;
            __syncthreads();
            sh[tid] += t;
            __syncthreads();
        }
        if (i < N_NODES) {
            int inc = carry + sh[tid];
            g_rowptr[i + 1] = inc;
            g_cursor[i] = inc - vv;
        }
        __syncthreads();
        if (tid == 0) carry += sh[1023];
        __syncthreads();
    }
}

__global__ void fill_kernel(const int* __restrict__ dst) {
    int e = blockIdx.x * blockDim.x + threadIdx.x;
    if (e < N_EDGES) {
        int pos = atomicAdd(&g_cursor[dst[e]], 1);
        g_perm[pos] = e;
    }
}

// ---------------- degree-descending node order (counting sort) --------------
// bin = DBINS-1 - min(deg, DBINS-1): descending degree after ascending-bin sort
__global__ void deg_hist_kernel() {
    int i = blockIdx.x * blockDim.x + threadIdx.x;
    if (i < N_NODES) {
        int d = g_rowptr[i + 1] - g_rowptr[i];
        int b = (DBINS - 1) - min(d, DBINS - 1);
        atomicAdd(&g_hcnt[b], 1);
    }
}

// exclusive scan over DBINS bins (single block); leaves cursors in g_hcnt
__global__ void deg_scan_kernel() {
    __shared__ int sh[DBINS];
    int tid = threadIdx.x;
    int v = g_hcnt[tid];
    sh[tid] = v;
    __syncthreads();
    #pragma unroll
    for (int off = 1; off < DBINS; off <<= 1) {
        int t = (tid >= off) ? sh[tid - off] : 0;
        __syncthreads();
        sh[tid] += t;
        __syncthreads();
    }
    g_hcnt[tid] = sh[tid] - v;   // exclusive prefix -> scatter cursor
}

__global__ void deg_scatter_kernel() {
    int i = blockIdx.x * blockDim.x + threadIdx.x;
    if (i < N_NODES) {
        int d = g_rowptr[i + 1] - g_rowptr[i];
        int b = (DBINS - 1) - min(d, DBINS - 1);
        int pos = atomicAdd(&g_hcnt[b], 1);
        g_order[pos] = i;
    }
}

// ---------------- embedding: u = [x@W_emb+b | t@W_t+b | s@W_s+b] ------------
__global__ __launch_bounds__(256) void embed_kernel(
    const float* __restrict__ x, const float* __restrict__ t,
    const float* __restrict__ s,
    const float* __restrict__ W_emb, const float* __restrict__ b_emb,
    const float* __restrict__ W_t, const float* __restrict__ b_t,
    const float* __restrict__ W_s, const float* __restrict__ b_s)
{
    __shared__ float xs[IN_FLAT + T_DIM + S_DIM];
    int node = blockIdx.x;
    int tid  = threadIdx.x;
    if (tid < IN_FLAT) xs[tid] = x[node * IN_FLAT + tid];
    else if (tid < IN_FLAT + T_DIM) xs[tid] = t[node * T_DIM + (tid - IN_FLAT)];
    else if (tid < IN_FLAT + T_DIM + S_DIM)
        xs[tid] = s[node * S_DIM + (tid - IN_FLAT - T_DIM)];
    __syncthreads();

    float a = b_emb[tid];
    #pragma unroll
    for (int k = 0; k < IN_FLAT; k++) a = fmaf(xs[k], W_emb[k * HID + tid], a);
    float tt = b_t[tid];
    #pragma unroll
    for (int k = 0; k < T_DIM; k++) tt = fmaf(xs[IN_FLAT + k], W_t[k * HID + tid], tt);
    float ss = b_s[tid];
    #pragma unroll
    for (int k = 0; k < S_DIM; k++)
        ss = fmaf(xs[IN_FLAT + T_DIM + k], W_s[k * HID + tid], ss);

    g_u[node * 768 + tid]       = a;
    g_u[node * 768 + 256 + tid] = tt;
    g_u[node * 768 + 512 + tid] = ss;
}

// ---------------- tf32 tensor-core GEMM ------------------------------------
__device__ __forceinline__ unsigned f2tf32(float x) {
    unsigned r;
    asm("cvt.rna.tf32.f32 %0, %1;" : "=r"(r) : "f"(x));
    return r;
}

__global__ __launch_bounds__(256) void gemm_tf32_kernel(
    const float* __restrict__ A, int M, int K,
    const float* __restrict__ W0, const float* __restrict__ W1,
    const float* __restrict__ W2, const float* __restrict__ W3,
    const float* __restrict__ b0, const float* __restrict__ b1,
    const float* __restrict__ b2, const float* __restrict__ b3,
    float* __restrict__ C0, float* __restrict__ C1,
    float* __restrict__ C2, float* __restrict__ C3)
{
    const float* W; const float* bias; float* C;
    switch (blockIdx.z) {
        case 0: W = W0; bias = b0; C = C0; break;
        case 1: W = W1; bias = b1; C = C1; break;
        case 2: W = W2; bias = b2; C = C2; break;
        default: W = W3; bias = b3; C = C3; break;
    }

    __shared__ unsigned As[4096];
    __shared__ unsigned Bs[4096];

    int tid = threadIdx.x;
    int lane = tid & 31, warp = tid >> 5;
    int wm = warp >> 1, wn = warp & 1;
    int m0 = blockIdx.y * 128;
    int n0 = blockIdx.x * 128;

    float acc[2][8][4];
    #pragma unroll
    for (int mt = 0; mt < 2; mt++)
        #pragma unroll
        for (int j = 0; j < 8; j++)
            #pragma unroll
            for (int r = 0; r < 4; r++) acc[mt][j][r] = 0.f;

    for (int k0 = 0; k0 < K; k0 += 32) {
        #pragma unroll
        for (int i = 0; i < 4; i++) {
            int idx = tid + 256 * i;
            int row = idx >> 3;
            int c4  = idx & 7;
            int gr = m0 + row;
            float4 av = make_float4(0.f, 0.f, 0.f, 0.f);
            if (gr < M)
                av = *reinterpret_cast<const float4*>(A + (size_t)gr * K + k0 + c4 * 4);
            float vv[4] = {av.x, av.y, av.z, av.w};
            int tm = row >> 4, mr = row & 15;
            #pragma unroll
            for (int j = 0; j < 4; j++) {
                int kl = c4 * 4 + j;
                int tk = kl >> 3, kr = kl & 7;
                int ln = ((mr & 7) << 2) | (kr & 3);
                int rg = (mr >> 3) | ((kr >> 2) << 1);
                As[(((tm * 4 + tk) * 32 + ln) << 2) + rg] = f2tf32(vv[j]);
            }
        }
        #pragma unroll
        for (int i = 0; i < 4; i++) {
            int idx = tid + 256 * i;
            int kl = idx >> 5;
            int c4 = idx & 31;
            float4 bv = *reinterpret_cast<const float4*>(
                W + (size_t)(k0 + kl) * HID + n0 + c4 * 4);
            float vv[4] = {bv.x, bv.y, bv.z, bv.w};
            int tk = kl >> 3, kr = kl & 7;
            #pragma unroll
            for (int j = 0; j < 4; j++) {
                int nl = c4 * 4 + j;
                int tn = nl >> 3, nr = nl & 7;
                int ln = (nr << 2) | (kr & 3);
                int rg = kr >> 2;
                Bs[(((tn * 4 + tk) * 32 + ln) << 1) + rg] = f2tf32(vv[j]);
            }
        }
        __syncthreads();

        #pragma unroll
        for (int tk = 0; tk < 4; tk++) {
            uint4 af[2];
            #pragma unroll
            for (int mt = 0; mt < 2; mt++)
                af[mt] = *reinterpret_cast<const uint4*>(
                    &As[(((wm * 2 + mt) * 4 + tk) * 32 + lane) << 2]);
            uint2 bf[8];
            #pragma unroll
            for (int j = 0; j < 8; j++)
                bf[j] = *reinterpret_cast<const uint2*>(
                    &Bs[(((wn * 8 + j) * 4 + tk) * 32 + lane) << 1]);
            #pragma unroll
            for (int mt = 0; mt < 2; mt++)
                #pragma unroll
                for (int j = 0; j < 8; j++) {
                    asm volatile(
                        "mma.sync.aligned.m16n8k8.row.col.f32.tf32.tf32.f32 "
                        "{%0,%1,%2,%3},{%4,%5,%6,%7},{%8,%9},{%0,%1,%2,%3};\n"
                        : "+f"(acc[mt][j][0]), "+f"(acc[mt][j][1]),
                          "+f"(acc[mt][j][2]), "+f"(acc[mt][j][3])
                        : "r"(af[mt].x), "r"(af[mt].y), "r"(af[mt].z), "r"(af[mt].w),
                          "r"(bf[j].x), "r"(bf[j].y));
                }
        }
        __syncthreads();
    }

    #pragma unroll
    for (int j = 0; j < 8; j++) {
        int col = n0 + (wn * 8 + j) * 8 + 2 * (lane & 3);
        float bx = bias[col], by = bias[col + 1];
        #pragma unroll
        for (int mt = 0; mt < 2; mt++) {
            int r0 = m0 + (wm * 2 + mt) * 16 + (lane >> 2);
            if (r0 < M) {
                float2 o = make_float2(acc[mt][j][0] + bx, acc[mt][j][1] + by);
                *reinterpret_cast<float2*>(C + (size_t)r0 * HID + col) = o;
            }
            int r1 = r0 + 8;
            if (r1 < M) {
                float2 o = make_float2(acc[mt][j][2] + bx, acc[mt][j][3] + by);
                *reinterpret_cast<float2*>(C + (size_t)r1 * HID + col) = o;
            }
        }
    }
}

// ---------------- layernorm + relu (in place on g_h) ------------------------
__global__ __launch_bounds__(256) void ln_relu_kernel(
    const float* __restrict__ gam, const float* __restrict__ bet,
    float* __restrict__ h)
{
    int node = blockIdx.x, tid = threadIdx.x;
    float v = h[node * HID + tid];
    __shared__ float red[8];

    float s1 = v;
    #pragma unroll
    for (int o = 16; o; o >>= 1) s1 += __shfl_xor_sync(0xffffffffu, s1, o);
    if ((tid & 31) == 0) red[tid >> 5] = s1;
    __syncthreads();
    float tot = 0.f;
    #pragma unroll
    for (int i = 0; i < 8; i++) tot += red[i];
    float mu = tot * (1.0f / HID);
    float d = v - mu;

    float s2 = d * d;
    #pragma unroll
    for (int o = 16; o; o >>= 1) s2 += __shfl_xor_sync(0xffffffffu, s2, o);
    __syncthreads();
    if ((tid & 31) == 0) red[tid >> 5] = s2;
    __syncthreads();
    float tot2 = 0.f;
    #pragma unroll
    for (int i = 0; i < 8; i++) tot2 += red[i];
    float var = tot2 * (1.0f / HID);

    float y = d * rsqrtf(var + 1e-5f) * gam[tid] + bet[tid];
    h[node * HID + tid] = fmaxf(y, 0.f);
}

// ---------------- qprep: qe8[n] = We @ q[n], qbe[n] = be . q[n] -------------
__global__ __launch_bounds__(256) void qprep_kernel(
    const float* __restrict__ q, const float* __restrict__ We,
    const float* __restrict__ be,
    float* __restrict__ qe8, float* __restrict__ qbe)
{
    int warp = (blockIdx.x * blockDim.x + threadIdx.x) >> 5;
    int lane = threadIdx.x & 31;
    if (warp >= N_NODES) return;
    float qr[8];
    #pragma unroll
    for (int i = 0; i < 8; i++) qr[i] = q[(size_t)warp * HID + lane + 32 * i];

    float part[9];
    #pragma unroll
    for (int j = 0; j < 8; j++) {
        float p = 0.f;
        #pragma unroll
        for (int i = 0; i < 8; i++)
            p = fmaf(qr[i], We[j * HID + lane + 32 * i], p);
        part[j] = p;
    }
    {
        float p = 0.f;
        #pragma unroll
        for (int i = 0; i < 8; i++) p = fmaf(qr[i], be[lane + 32 * i], p);
        part[8] = p;
    }
    #pragma unroll
    for (int o = 16; o; o >>= 1)
        #pragma unroll
        for (int j = 0; j < 9; j++)
            part[j] += __shfl_xor_sync(0xffffffffu, part[j], o);
    if (lane < 8) qe8[warp * EDGE_DIM + lane] = part[lane];
    if (lane == 0) qbe[warp] = part[8];
}

// ---------------- edge attention: warp per destination node -----------------
// R5 body; warps pick nodes via degree-descending g_order so the 8 warps of a
// block carry near-equal degree (removes max-of-8 imbalance per block).
__global__ __launch_bounds__(256, 2) void edge_attn_kernel(
    const int* __restrict__ src, const float* __restrict__ edge_attr,
    const float* __restrict__ We, const float* __restrict__ be,
    const float* __restrict__ q, const float* __restrict__ k,
    const float* __restrict__ v, const float* __restrict__ skp,
    const float* __restrict__ qe8, const float* __restrict__ qbe,
    float* __restrict__ h_out)
{
    int wid = (blockIdx.x * blockDim.x + threadIdx.x) >> 5;
    int lane = threadIdx.x & 31;
    if (wid >= N_NODES) return;
    int node = g_order[wid];

    float qr[8];
    #pragma unroll
    for (int i = 0; i < 8; i++) qr[i] = q[(size_t)node * HID + lane + 32 * i];
    float qe8v = (lane < 8) ? qe8[node * EDGE_DIM + lane] : 0.f;
    float qbev = qbe[node];

    float acc[8];
    #pragma unroll
    for (int i = 0; i < 8; i++) acc[i] = 0.f;
    float accE = 0.f;
    float l = 0.f;

    int beg = g_rowptr[node], end = g_rowptr[node + 1];
    int p = beg;

    for (; p + 4 <= end; p += 4) {
        int e0 = g_perm[p],     e1 = g_perm[p + 1];
        int e2 = g_perm[p + 2], e3 = g_perm[p + 3];
        int s0 = src[e0], s1 = src[e1], s2 = src[e2], s3 = src[e3];
        float ea0 = (lane < 8) ? edge_attr[(size_t)e0 * EDGE_DIM + lane] : 0.f;
        float ea1 = (lane < 8) ? edge_attr[(size_t)e1 * EDGE_DIM + lane] : 0.f;
        float ea2 = (lane < 8) ? edge_attr[(size_t)e2 * EDGE_DIM + lane] : 0.f;
        float ea3 = (lane < 8) ? edge_attr[(size_t)e3 * EDGE_DIM + lane] : 0.f;
        const float* k0 = k + (size_t)s0 * HID + lane;
        const float* k1 = k + (size_t)s1 * HID + lane;
        const float* k2 = k + (size_t)s2 * HID + lane;
        const float* k3 = k + (size_t)s3 * HID + lane;

        float d0 = ea0 * qe8v, d1 = ea1 * qe8v;
        float d2 = ea2 * qe8v, d3 = ea3 * qe8v;
        #pragma unroll
        for (int i = 0; i < 8; i++) {
            d0 = fmaf(qr[i], k0[32 * i], d0);
            d1 = fmaf(qr[i], k1[32 * i], d1);
            d2 = fmaf(qr[i], k2[32 * i], d2);
            d3 = fmaf(qr[i], k3[32 * i], d3);
        }
        #pragma unroll
        for (int o = 16; o; o >>= 1) {
            d0 += __shfl_xor_sync(0xffffffffu, d0, o);
            d1 += __shfl_xor_sync(0xffffffffu, d1, o);
            d2 += __shfl_xor_sync(0xffffffffu, d2, o);
            d3 += __shfl_xor_sync(0xffffffffu, d3, o);
        }
        float pw0 = __expf((d0 + qbev) * 0.0625f);
        float pw1 = __expf((d1 + qbev) * 0.0625f);
        float pw2 = __expf((d2 + qbev) * 0.0625f);
        float pw3 = __expf((d3 + qbev) * 0.0625f);
        l += (pw0 + pw1) + (pw2 + pw3);
        accE = fmaf(pw0, ea0, accE);
        accE = fmaf(pw1, ea1, accE);
        accE = fmaf(pw2, ea2, accE);
        accE = fmaf(pw3, ea3, accE);
        const float* v0 = v + (size_t)s0 * HID + lane;
        const float* v1 = v + (size_t)s1 * HID + lane;
        const float* v2 = v + (size_t)s2 * HID + lane;
        const float* v3 = v + (size_t)s3 * HID + lane;
        #pragma unroll
        for (int i = 0; i < 8; i++) {
            float t0 = fmaf(pw0, v0[32 * i], pw1 * v1[32 * i]);
            float t1 = fmaf(pw2, v2[32 * i], pw3 * v3[32 * i]);
            acc[i] += t0 + t1;
        }
    }
    for (; p < end; p++) {
        int e0 = g_perm[p];
        int s0 = src[e0];
        float ea0 = (lane < 8) ? edge_attr[(size_t)e0 * EDGE_DIM + lane] : 0.f;
        const float* k0 = k + (size_t)s0 * HID + lane;
        float d0 = ea0 * qe8v;
        #pragma unroll
        for (int i = 0; i < 8; i++) d0 = fmaf(qr[i], k0[32 * i], d0);
        #pragma unroll
        for (int o = 16; o; o >>= 1) d0 += __shfl_xor_sync(0xffffffffu, d0, o);
        float pw0 = __expf((d0 + qbev) * 0.0625f);
        l += pw0;
        accE = fmaf(pw0, ea0, accE);
        const float* v0 = v + (size_t)s0 * HID + lane;
        #pragma unroll
        for (int i = 0; i < 8; i++) acc[i] = fmaf(pw0, v0[32 * i], acc[i]);
    }

    // epilogue: out = (acc + accE@We + l*be)/l + skip, relu
    float accEj[8];
    #pragma unroll
    for (int j = 0; j < 8; j++)
        accEj[j] = __shfl_sync(0xffffffffu, accE, j);
    float inv = 1.0f / (l + 1e-16f);
    #pragma unroll
    for (int i = 0; i < 8; i++) {
        int c = lane + 32 * i;
        float corr = l * be[c];
        #pragma unroll
        for (int j = 0; j < 8; j++)
            corr = fmaf(accEj[j], We[j * HID + c], corr);
        float o = (acc[i] + corr) * inv + skp[(size_t)node * HID + c];
        h_out[(size_t)node * HID + c] = fmaxf(o, 0.f);
    }
}

// ---------------- decoder: out = h @ W_dec + b_dec --------------------------
__global__ __launch_bounds__(256) void decoder_kernel(
    const float* __restrict__ h, const float* __restrict__ Wd,
    const float* __restrict__ bd, float* __restrict__ out)
{
    __shared__ float Ws[HID * OUT_DIM];
    for (int i = threadIdx.x; i < HID * OUT_DIM; i += blockDim.x) Ws[i] = Wd[i];
    __syncthreads();
    for (int idx = blockIdx.x * blockDim.x + threadIdx.x; idx < N_NODES * OUT_DIM;
         idx += gridDim.x * blockDim.x) {
        int node = idx / OUT_DIM;
        int c = idx - node * OUT_DIM;
        float sum = bd[c];
        const float* hr = h + (size_t)node * HID;
        #pragma unroll 8
        for (int k2 = 0; k2 < HID; k2++)
            sum = fmaf(hr[k2], Ws[k2 * OUT_DIM + c], sum);
        out[idx] = sum;
    }
}

// ---------------- launch ----------------------------------------------------
extern "C" void kernel_launch(void* const* d_in, const int* in_sizes, int n_in,
                              void* d_out, int out_size)
{
    const float* x        = (const float*)d_in[0];
    const int*   edge_idx = (const int*)  d_in[1];
    const float* edge_attr= (const float*)d_in[2];
    const float* t        = (const float*)d_in[3];
    const float* s        = (const float*)d_in[4];
    const float* W_emb    = (const float*)d_in[5];
    const float* b_emb    = (const float*)d_in[6];
    const float* W_t      = (const float*)d_in[7];
    const float* b_t      = (const float*)d_in[8];
    const float* W_s      = (const float*)d_in[9];
    const float* b_s      = (const float*)d_in[10];
    const float* W_f      = (const float*)d_in[11];
    const float* b_f      = (const float*)d_in[12];
    const float* ln_g     = (const float*)d_in[13];
    const float* ln_b     = (const float*)d_in[14];
    const float* Wq       = (const float*)d_in[15];
    const float* bq       = (const float*)d_in[16];
    const float* Wk       = (const float*)d_in[17];
    const float* bk       = (const float*)d_in[18];
    const float* Wv       = (const float*)d_in[19];
    const float* bv       = (const float*)d_in[20];
    const float* We       = (const float*)d_in[21];
    const float* be       = (const float*)d_in[22];
    const float* Wskip    = (const float*)d_in[23];
    const float* bskip    = (const float*)d_in[24];
    const float* W_dec    = (const float*)d_in[25];
    const float* b_dec    = (const float*)d_in[26];
    float* out = (float*)d_out;

    const int* src = edge_idx;
    const int* dst = edge_idx + N_EDGES;

    float *p_h, *p_u, *p_q, *p_k, *p_v, *p_skip, *p_qe8, *p_qbe;
    cudaGetSymbolAddress((void**)&p_h, g_h);
    cudaGetSymbolAddress((void**)&p_u, g_u);
    cudaGetSymbolAddress((void**)&p_q, g_q);
    cudaGetSymbolAddress((void**)&p_k, g_k);
    cudaGetSymbolAddress((void**)&p_v, g_v);
    cudaGetSymbolAddress((void**)&p_skip, g_skip);
    cudaGetSymbolAddress((void**)&p_qe8, g_qe8);
    cudaGetSymbolAddress((void**)&p_qbe, g_qbe);

    // CSR by destination + degree-descending node order
    zero_cnt_kernel<<<80, 256>>>();
    count_kernel<<<(N_EDGES + 255) / 256, 256>>>(dst);
    scan_kernel<<<1, 1024>>>();
    fill_kernel<<<(N_EDGES + 255) / 256, 256>>>(dst);
    deg_hist_kernel<<<(N_NODES + 255) / 256, 256>>>();
    deg_scan_kernel<<<1, DBINS>>>();
    deg_scatter_kernel<<<(N_NODES + 255) / 256, 256>>>();

    // spatio-temporal embedding + fusion GEMM + LN + relu
    embed_kernel<<<N_NODES, 256>>>(x, t, s, W_emb, b_emb, W_t, b_t, W_s, b_s);
    dim3 fgrid(2, (N_NODES + 127) / 128, 1);
    gemm_tf32_kernel<<<fgrid, 256>>>(p_u, N_NODES, 3 * HID,
        W_f, W_f, W_f, W_f, b_f, b_f, b_f, b_f, p_h, p_h, p_h, p_h);
    ln_relu_kernel<<<N_NODES, 256>>>(ln_g, ln_b, p_h);

    // 5 TransformerConv layers
    dim3 qgrid(2, (N_NODES + 127) / 128, 4);
    int warps_grid = (N_NODES * 32 + 255) / 256;
    for (int l = 0; l < N_LAYERS; l++) {
        const float* We_l = We + (size_t)l * EDGE_DIM * HID;
        const float* be_l = be + l * HID;
        gemm_tf32_kernel<<<qgrid, 256>>>(p_h, N_NODES, HID,
            Wq + (size_t)l * HID * HID, Wk + (size_t)l * HID * HID,
            Wv + (size_t)l * HID * HID, Wskip + (size_t)l * HID * HID,
            bq + l * HID, bk + l * HID, bv + l * HID, bskip + l * HID,
            p_q, p_k, p_v, p_skip);
        qprep_kernel<<<warps_grid, 256>>>(p_q, We_l, be_l, p_qe8, p_qbe);
        edge_attn_kernel<<<warps_grid, 256>>>(
            src, edge_attr, We_l, be_l, p_q, p_k, p_v, p_skip,
            p_qe8, p_qbe, p_h);
    }

    // decoder
    decoder_kernel<<<592, 256>>>(p_h, W_dec, b_dec, out);
}